// round 10
// baseline (speedup 1.0000x reference)
#include <cuda_runtime.h>
#include <cuda_bf16.h>

// ---------------------------------------------------------------------------
// BiRNN R10: R8 base (4 lanes/chain, 1 chain/thread, 128x256 -> 2 warps/SMSP,
// f32x2 row pairs, exact EX2/RCP tanh with SC-prescaled weights) plus:
//   * depth-1 shfl.idx broadcast (6 shfls, no 2-stage chain)
//   * per-group precomputed x-contribution (XC) pipelined across STEP blocks
// ---------------------------------------------------------------------------

typedef unsigned long long u64t;

__device__ float g_y[4096 * 18];  // concat(h_fwd, h_bwd) staging

static constexpr float SC = 2.8853900817779268f;  // 2 * log2(e)

__device__ __forceinline__ u64t pk2(float lo, float hi) {
    u64t r;
    asm("mov.b64 %0, {%1, %2};" : "=l"(r) : "f"(lo), "f"(hi));
    return r;
}
__device__ __forceinline__ void upk2(u64t v, float& lo, float& hi) {
    asm("mov.b64 {%0, %1}, %2;" : "=f"(lo), "=f"(hi) : "l"(v));
}
__device__ __forceinline__ u64t f2fma(u64t a, u64t b, u64t c) {
    u64t r;
    asm("fma.rn.f32x2 %0, %1, %2, %3;" : "=l"(r) : "l"(a), "l"(b), "l"(c));
    return r;
}
__device__ __forceinline__ u64t f2add(u64t a, u64t b) {
    u64t r;
    asm("add.rn.f32x2 %0, %1, %2;" : "=l"(r) : "l"(a), "l"(b));
    return r;
}
__device__ __forceinline__ float ex2f_(float x) {
    float r; asm("ex2.approx.f32 %0, %1;" : "=f"(r) : "f"(x)); return r;
}
__device__ __forceinline__ float rcpf_(float x) {
    float r; asm("rcp.approx.f32 %0, %1;" : "=f"(r) : "f"(x)); return r;
}
// s = 2*log2(e)*a ; tanh(a) = 1 - 2/(exp(2a)+1), exact identity, approx units
__device__ __forceinline__ float tanh_sc(float s) {
    float e = ex2f_(s);
    return fmaf(-2.0f, rcpf_(e + 1.0f), 1.0f);
}
__device__ __forceinline__ float getc(const float4& v, int m) {
    return m == 0 ? v.x : (m == 1 ? v.y : (m == 2 ? v.z : v.w));
}

// ---------------------------------------------------------------------------
// RNN1: lane r of 4 owns rows (2r, 2r+1) as one f32x2 pair; row 8 redundant.
// Local h slot k -> global column:
//   k0,k1 : 2r, 2r+1      k2,k3 : 2(r^1), +1
//   k4,k5 : 2(r^2), +1    k6,k7 : 2(r^3), +1      k8 : 8
// Broadcast: 6 depth-1 shfl.idx from lanes base|(r^1), base|(r^2), base|(r^3).
// ---------------------------------------------------------------------------
template <bool BACK>
__device__ __forceinline__ void rnn1_body(
    int b, int r, int s1, int s2, int s3, const float* __restrict__ x,
    const float* __restrict__ wih, const float* __restrict__ whh,
    const float* __restrict__ bih, const float* __restrict__ bhh, int T)
{
    const int row0 = 2 * r, row1 = 2 * r + 1;
    int cmap[9];
    cmap[0] = 2 * r;       cmap[1] = 2 * r + 1;
    cmap[2] = 2 * (r ^ 1); cmap[3] = 2 * (r ^ 1) + 1;
    cmap[4] = 2 * (r ^ 2); cmap[5] = 2 * (r ^ 2) + 1;
    cmap[6] = 2 * (r ^ 3); cmap[7] = 2 * (r ^ 3) + 1;
    cmap[8] = 8;

    // ---- weights (pre-scaled by SC), per-lane permuted columns
    u64t WH[9]; float W8[9];
#pragma unroll
    for (int k = 0; k < 9; k++) {
        int c = cmap[k];
        WH[k] = pk2(SC * __ldg(whh + row0 * 9 + c), SC * __ldg(whh + row1 * 9 + c));
        W8[k] = SC * __ldg(whh + 72 + c);
    }
    u64t WI[5]; float WI8[5];
#pragma unroll
    for (int d = 0; d < 5; d++) {
        WI[d] = pk2(SC * __ldg(wih + row0 * 5 + d), SC * __ldg(wih + row1 * 5 + d));
        WI8[d] = SC * __ldg(wih + 40 + d);
    }
    u64t BI = pk2(SC * (__ldg(bih + row0) + __ldg(bhh + row0)),
                  SC * (__ldg(bih + row1) + __ldg(bhh + row1)));
    float B8 = SC * (__ldg(bih + 8) + __ldg(bhh + 8));

    // ---- state
    float vs[9];
    u64t  vb[9];
#pragma unroll
    for (int i = 0; i < 9; i++) { vs[i] = 0.0f; vb[i] = 0ULL; }

    const int G = T >> 2;  // 4 steps/group = 20 floats = 5 float4
    const float4* xp = reinterpret_cast<const float4*>(x) + (size_t)b * ((size_t)T * 5 / 4);

    float4 bA[5], bB[5];
    u64t  xcA[4], xcB[4];
    float x8A[4], x8B[4];

    auto LOADG = [&](float4 (&buf)[5], int g) {
        int base = BACK ? 5 * (G - 1 - g) : 5 * g;
#pragma unroll
        for (int k = 0; k < 5; k++) buf[k] = __ldg(xp + base + k);
    };

    // precompute bias + x-dot for the 4 steps of a group (h-independent)
    auto XC = [&](const float4 (&bf)[5], u64t (&xc)[4], float (&x8)[4]) {
#pragma unroll
        for (int s = 0; s < 4; s++) {
            int off = (BACK ? (3 - s) : s) * 5;
            u64t a = BI; float a8 = B8;
#pragma unroll
            for (int d = 0; d < 5; d++) {
                int idx = off + d;
                float xv = getc(bf[idx >> 2], idx & 3);
                a = f2fma(WI[d], pk2(xv, xv), a);
                a8 = fmaf(WI8[d], xv, a8);
            }
            xc[s] = a; x8[s] = a8;
        }
    };

    auto STEP = [&](u64t xc, float x8) {
        u64t a = xc, ah = 0ULL;
        float a8x = x8, a8y = 0.0f;
#pragma unroll
        for (int k = 0; k < 5; k++) {
            a = f2fma(WH[k], vb[k], a);
            a8x = fmaf(W8[k], vs[k], a8x);
        }
#pragma unroll
        for (int k = 5; k < 9; k++) {
            ah = f2fma(WH[k], vb[k], ah);
            a8y = fmaf(W8[k], vs[k], a8y);
        }
        u64t av = f2add(a, ah);
        float a8 = a8x + a8y;
        float t0, t1;
        upk2(av, t0, t1);
        float o0 = tanh_sc(t0), o1 = tanh_sc(t1), o8 = tanh_sc(a8);
        // depth-1 permutation broadcast (all 6 shfls depend only on o0/o1)
        vs[0] = o0; vs[1] = o1;
        vs[2] = __shfl_sync(0xffffffffu, o0, s1);
        vs[3] = __shfl_sync(0xffffffffu, o1, s1);
        vs[4] = __shfl_sync(0xffffffffu, o0, s2);
        vs[5] = __shfl_sync(0xffffffffu, o1, s2);
        vs[6] = __shfl_sync(0xffffffffu, o0, s3);
        vs[7] = __shfl_sync(0xffffffffu, o1, s3);
        vs[8] = o8;
#pragma unroll
        for (int i = 0; i < 9; i++) vb[i] = pk2(vs[i], vs[i]);
    };

    LOADG(bA, 0);
    XC(bA, xcA, x8A);
    for (int g = 0; g < G; g += 2) {
        if (g + 1 < G) LOADG(bB, g + 1);
#pragma unroll
        for (int s = 0; s < 4; s++) STEP(xcA[s], x8A[s]);
        if (g + 1 < G) XC(bB, xcB, x8B);      // fills next steps' stall slots
        if (g + 2 < G) LOADG(bA, g + 2);
#pragma unroll
        for (int s = 0; s < 4; s++) STEP(xcB[s], x8B[s]);
        if (g + 2 < G) XC(bA, xcA, x8A);
    }

    // writeback: own rows + row 8 (identical on all lanes -> benign dup store)
    float* dst = g_y + (size_t)b * 18 + (BACK ? 9 : 0);
    dst[row0] = vs[0]; dst[row1] = vs[1]; dst[8] = vs[8];
}

__global__ void __launch_bounds__(256, 1) rnn1_kernel(
    const float* __restrict__ x,
    const float* __restrict__ wih_f, const float* __restrict__ whh_f,
    const float* __restrict__ bih_f, const float* __restrict__ bhh_f,
    const float* __restrict__ wih_b, const float* __restrict__ whh_b,
    const float* __restrict__ bih_b, const float* __restrict__ bhh_b,
    int T, int B)
{
    int gtid = blockIdx.x * blockDim.x + threadIdx.x;
    int lane = threadIdx.x & 31;
    int r    = lane & 3;
    int base = lane & ~3;
    int s1 = base | (r ^ 1), s2 = base | (r ^ 2), s3 = base | (r ^ 3);
    int chain = gtid >> 2;         // [0, 2B); first B fwd, second B bwd
    if (chain < B) {
        rnn1_body<false>(chain, r, s1, s2, s3, x, wih_f, whh_f, bih_f, bhh_f, T);
    } else {
        rnn1_body<true>(chain - B, r, s1, s2, s3, x, wih_b, whh_b, bih_b, bhh_b, T);
    }
}

// ---------------------------------------------------------------------------
// RNN2 + projection: warp per batch, smem h-broadcast, split accumulators.
// (identical to R8 version, best measured: ~21us)
// ---------------------------------------------------------------------------
#define ROWF 36  // padded row stride (floats): 16B-aligned, conflict-free

__global__ void __launch_bounds__(128) rnn2_kernel(
    const float* __restrict__ wih2, const float* __restrict__ whh2,
    const float* __restrict__ bih2, const float* __restrict__ bhh2,
    const float* __restrict__ wout, const float* __restrict__ bout,
    float* __restrict__ out, int B)
{
    __shared__ __align__(16) float hbuf[4][25 * ROWF];
    __shared__ float wsm[96];

    int tid = threadIdx.x;
    int wid = tid >> 5;
    int lane = tid & 31;
    int b = blockIdx.x * 4 + wid;

    if (tid < 96) wsm[tid] = __ldg(wout + tid);
    __syncthreads();
    if (b >= B) return;

    float WHR[32];
    {
        const float4* wr = reinterpret_cast<const float4*>(whh2 + lane * 32);
#pragma unroll
        for (int q = 0; q < 8; q++) {
            float4 v = __ldg(wr + q);
            WHR[4 * q + 0] = SC * v.x; WHR[4 * q + 1] = SC * v.y;
            WHR[4 * q + 2] = SC * v.z; WHR[4 * q + 3] = SC * v.w;
        }
    }
    float bi = SC * (__ldg(bih2 + lane) + __ldg(bhh2 + lane));

    // step 0: input y from g_y, two partial chains
    const float* yb = g_y + (size_t)b * 18;
    float ac0 = bi, ac1 = 0.0f;
#pragma unroll
    for (int j = 0; j < 9; j++)
        ac0 = fmaf(SC * __ldg(wih2 + lane * 18 + j), __ldg(yb + j), ac0);
#pragma unroll
    for (int j = 9; j < 18; j++)
        ac1 = fmaf(SC * __ldg(wih2 + lane * 18 + j), __ldg(yb + j), ac1);
    float h = tanh_sc(ac0 + ac1);

    float* hr = hbuf[wid];
    hr[lane] = h;
    __syncwarp();

#pragma unroll 1
    for (int t = 1; t < 25; t++) {
        const float4* rp = reinterpret_cast<const float4*>(hr + (t - 1) * ROWF);
        float p0 = bi, p1 = 0.0f, p2 = 0.0f, p3 = 0.0f;
#pragma unroll
        for (int q = 0; q < 8; q++) {
            float4 v = rp[q];
            float* pp = (q < 2) ? &p0 : ((q < 4) ? &p1 : ((q < 6) ? &p2 : &p3));
            *pp = fmaf(WHR[4 * q + 0], v.x, *pp);
            *pp = fmaf(WHR[4 * q + 1], v.y, *pp);
            *pp = fmaf(WHR[4 * q + 2], v.z, *pp);
            *pp = fmaf(WHR[4 * q + 3], v.w, *pp);
        }
        h = tanh_sc((p0 + p1) + (p2 + p3));
        hr[t * ROWF + lane] = h;
        __syncwarp();
    }

    // epilogue: 75 outputs -> lanes (idx = lane, lane+32, lane+64)
    float bo0 = __ldg(bout + 0), bo1 = __ldg(bout + 1), bo2 = __ldg(bout + 2);
    float* ob = out + (size_t)b * 75;
#pragma unroll
    for (int k = 0; k < 3; k++) {
        int idx = lane + 32 * k;
        if (idx < 75) {
            int t = idx / 3;
            int o = idx - 3 * t;
            const float4* rp = reinterpret_cast<const float4*>(hr + t * ROWF);
            float p0 = (o == 0) ? bo0 : ((o == 1) ? bo1 : bo2);
            float p1 = 0.0f, p2 = 0.0f, p3 = 0.0f;
#pragma unroll
            for (int q = 0; q < 8; q++) {
                float4 v = rp[q];
                float* pp = (q < 2) ? &p0 : ((q < 4) ? &p1 : ((q < 6) ? &p2 : &p3));
                *pp = fmaf(wsm[o * 32 + 4 * q + 0], v.x, *pp);
                *pp = fmaf(wsm[o * 32 + 4 * q + 1], v.y, *pp);
                *pp = fmaf(wsm[o * 32 + 4 * q + 2], v.z, *pp);
                *pp = fmaf(wsm[o * 32 + 4 * q + 3], v.w, *pp);
            }
            ob[idx] = (p0 + p1) + (p2 + p3);
        }
    }
}

// ---------------------------------------------------------------------------
extern "C" void kernel_launch(void* const* d_in, const int* in_sizes, int n_in,
                              void* d_out, int out_size)
{
    const float* x      = (const float*)d_in[0];
    const float* wih_f  = (const float*)d_in[1];
    const float* whh_f  = (const float*)d_in[2];
    const float* bih_f  = (const float*)d_in[3];
    const float* bhh_f  = (const float*)d_in[4];
    const float* wih_b  = (const float*)d_in[5];
    const float* whh_b  = (const float*)d_in[6];
    const float* bih_b  = (const float*)d_in[7];
    const float* bhh_b  = (const float*)d_in[8];
    const float* wih2   = (const float*)d_in[9];
    const float* whh2   = (const float*)d_in[10];
    const float* bih2   = (const float*)d_in[11];
    const float* bhh2   = (const float*)d_in[12];
    const float* wout   = (const float*)d_in[13];
    const float* bout   = (const float*)d_in[14];
    float* out = (float*)d_out;

    int B = out_size / 75;                 // 4096
    int T = in_sizes[0] / (B * 5);         // 2048

    // 4 lanes/chain, 1 chain/thread: 2B chains * 4 = 8*B threads.
    // Blocks of 256 -> 128 blocks -> 1 block/SM -> 2 warps per SMSP.
    int blocks1 = (8 * B) / 256;           // 128
    rnn1_kernel<<<blocks1, 256>>>(x, wih_f, whh_f, bih_f, bhh_f,
                                  wih_b, whh_b, bih_b, bhh_b, T, B);

    rnn2_kernel<<<B / 4, 128>>>(wih2, whh2, bih2, bhh2, wout, bout, out, B);
}

// round 11
// speedup vs baseline: 1.1781x; 1.1781x over previous
#include <cuda_runtime.h>
#include <cuda_bf16.h>

// ---------------------------------------------------------------------------
// BiRNN R11: exact R8 skeleton (best measured: 340.5us) + ONE change:
// 1-step x-dot lookahead placed in the tanh/shfl stall window of each step.
// 4 lanes/chain, 1 chain/thread, 128 blocks x 256 threads (2 warps/SMSP),
// f32x2 row pairs, exact EX2/RCP tanh with SC-prescaled weights.
// ---------------------------------------------------------------------------

typedef unsigned long long u64t;

__device__ float g_y[4096 * 18];  // concat(h_fwd, h_bwd) staging

static constexpr float SC = 2.8853900817779268f;  // 2 * log2(e)

__device__ __forceinline__ u64t pk2(float lo, float hi) {
    u64t r;
    asm("mov.b64 %0, {%1, %2};" : "=l"(r) : "f"(lo), "f"(hi));
    return r;
}
__device__ __forceinline__ void upk2(u64t v, float& lo, float& hi) {
    asm("mov.b64 {%0, %1}, %2;" : "=f"(lo), "=f"(hi) : "l"(v));
}
__device__ __forceinline__ u64t f2fma(u64t a, u64t b, u64t c) {
    u64t r;
    asm("fma.rn.f32x2 %0, %1, %2, %3;" : "=l"(r) : "l"(a), "l"(b), "l"(c));
    return r;
}
__device__ __forceinline__ u64t f2add(u64t a, u64t b) {
    u64t r;
    asm("add.rn.f32x2 %0, %1, %2;" : "=l"(r) : "l"(a), "l"(b));
    return r;
}
__device__ __forceinline__ float ex2f_(float x) {
    float r; asm("ex2.approx.f32 %0, %1;" : "=f"(r) : "f"(x)); return r;
}
__device__ __forceinline__ float rcpf_(float x) {
    float r; asm("rcp.approx.f32 %0, %1;" : "=f"(r) : "f"(x)); return r;
}
// s = 2*log2(e)*a ; tanh(a) = 1 - 2/(exp(2a)+1), exact identity, approx units
__device__ __forceinline__ float tanh_sc(float s) {
    float e = ex2f_(s);
    return fmaf(-2.0f, rcpf_(e + 1.0f), 1.0f);
}
__device__ __forceinline__ float getc(const float4& v, int m) {
    return m == 0 ? v.x : (m == 1 ? v.y : (m == 2 ? v.z : v.w));
}

// ---------------------------------------------------------------------------
// RNN1: lane r of 4 owns rows (2r, 2r+1) as one f32x2 pair; row 8 computed
// redundantly by all lanes (uniform stream). One chain per thread.
// Local h slot k -> global column (matches R8 butterfly):
//   k0,k1 : 2r, 2r+1           (own)
//   k2,k3 : 2(r^1), 2(r^1)+1   (shfl_xor 1)
//   k4..k7: 2(r^2), 2(r^2)+1, 2((r^2)^1), 2((r^2)^1)+1  (shfl_xor 2)
//   k8    : 8
// ---------------------------------------------------------------------------
template <bool BACK>
__device__ __forceinline__ void rnn1_body(
    int b, int r, const float* __restrict__ x,
    const float* __restrict__ wih, const float* __restrict__ whh,
    const float* __restrict__ bih, const float* __restrict__ bhh, int T)
{
    const int row0 = 2 * r, row1 = 2 * r + 1;
    int cmap[9];
    cmap[0] = 2 * r;             cmap[1] = 2 * r + 1;
    cmap[2] = 2 * (r ^ 1);       cmap[3] = 2 * (r ^ 1) + 1;
    cmap[4] = 2 * (r ^ 2);       cmap[5] = 2 * (r ^ 2) + 1;
    cmap[6] = 2 * ((r ^ 2) ^ 1); cmap[7] = 2 * ((r ^ 2) ^ 1) + 1;
    cmap[8] = 8;

    // ---- weights (pre-scaled by SC), per-lane permuted columns
    u64t WH[9]; float W8[9];
#pragma unroll
    for (int k = 0; k < 9; k++) {
        int c = cmap[k];
        WH[k] = pk2(SC * __ldg(whh + row0 * 9 + c), SC * __ldg(whh + row1 * 9 + c));
        W8[k] = SC * __ldg(whh + 72 + c);
    }
    u64t WI[5]; float WI8[5];
#pragma unroll
    for (int d = 0; d < 5; d++) {
        WI[d] = pk2(SC * __ldg(wih + row0 * 5 + d), SC * __ldg(wih + row1 * 5 + d));
        WI8[d] = SC * __ldg(wih + 40 + d);
    }
    u64t BI = pk2(SC * (__ldg(bih + row0) + __ldg(bhh + row0)),
                  SC * (__ldg(bih + row1) + __ldg(bhh + row1)));
    float B8 = SC * (__ldg(bih + 8) + __ldg(bhh + 8));

    // ---- state
    float vs[9];
    u64t  vb[9];
#pragma unroll
    for (int i = 0; i < 9; i++) { vs[i] = 0.0f; vb[i] = 0ULL; }

    const int G = T >> 2;  // 4 steps/group = 20 floats = 5 float4
    const float4* xp = reinterpret_cast<const float4*>(x) + (size_t)b * ((size_t)T * 5 / 4);

    float4 bA[5], bB[5];

    auto LOADG = [&](float4 (&buf)[5], int g) {
        int base = BACK ? 5 * (G - 1 - g) : 5 * g;
#pragma unroll
        for (int k = 0; k < 5; k++) buf[k] = __ldg(xp + base + k);
    };

    // bias + x-dot for one step (h-independent)
    auto XDOT = [&](const float4 (&bf)[5], int off, u64t& xc, float& x8) {
        u64t a = BI; float a8 = B8;
#pragma unroll
        for (int d = 0; d < 5; d++) {
            int idx = off + d;
            float xv = getc(bf[idx >> 2], idx & 3);
            a = f2fma(WI[d], pk2(xv, xv), a);
            a8 = fmaf(WI8[d], xv, a8);
        }
        xc = a; x8 = a8;
    };

    // one recurrence step: consume (xc,x8); compute NEXT step's (xc,x8) in the
    // tanh/shfl stall window (independent work keeps the issuer busy)
    auto HSTEP = [&](u64t xcur, float x8cur, u64t& nxc, float& nx8,
                     const float4 (&nbf)[5], int noff) {
        u64t a = xcur, ah = 0ULL;
        float a8x = x8cur, a8y = 0.0f;
#pragma unroll
        for (int k = 0; k < 5; k++) {
            a = f2fma(WH[k], vb[k], a);
            a8x = fmaf(W8[k], vs[k], a8x);
        }
#pragma unroll
        for (int k = 5; k < 9; k++) {
            ah = f2fma(WH[k], vb[k], ah);
            a8y = fmaf(W8[k], vs[k], a8y);
        }
        u64t av = f2add(a, ah);
        float a8 = a8x + a8y;
        // ---- lookahead: next step's x-dot (h-independent filler) ----
        XDOT(nbf, noff, nxc, nx8);
        // ---- tanh + broadcast ----
        float t0, t1;
        upk2(av, t0, t1);
        float o0 = tanh_sc(t0), o1 = tanh_sc(t1), o8 = tanh_sc(a8);
        float r0 = __shfl_xor_sync(0xffffffffu, o0, 1);
        float r1 = __shfl_xor_sync(0xffffffffu, o1, 1);
        float q0 = __shfl_xor_sync(0xffffffffu, o0, 2);
        float q1 = __shfl_xor_sync(0xffffffffu, o1, 2);
        float q2 = __shfl_xor_sync(0xffffffffu, r0, 2);
        float q3 = __shfl_xor_sync(0xffffffffu, r1, 2);
        vs[0] = o0; vs[1] = o1; vs[2] = r0; vs[3] = r1;
        vs[4] = q0; vs[5] = q1; vs[6] = q2; vs[7] = q3;
        vs[8] = o8;
#pragma unroll
        for (int i = 0; i < 9; i++) vb[i] = pk2(vs[i], vs[i]);
    };

    const int off0 = (BACK ? 3 : 0) * 5;   // first step's buffer offset

    LOADG(bA, 0);
    u64t xc; float x8;
    XDOT(bA, off0, xc, x8);

    for (int g = 0; g < G; g += 2) {
        if (g + 1 < G) LOADG(bB, g + 1);
#pragma unroll
        for (int s = 0; s < 4; s++) {
            if (s < 3) HSTEP(xc, x8, xc, x8, bA, (BACK ? (2 - s) : (s + 1)) * 5);
            else       HSTEP(xc, x8, xc, x8, bB, off0);
        }
        if (g + 2 < G) LOADG(bA, g + 2);
#pragma unroll
        for (int s = 0; s < 4; s++) {
            if (s < 3) HSTEP(xc, x8, xc, x8, bB, (BACK ? (2 - s) : (s + 1)) * 5);
            else       HSTEP(xc, x8, xc, x8, bA, off0);
        }
    }

    // writeback: own rows + row 8 (identical on all lanes -> benign dup store)
    float* dst = g_y + (size_t)b * 18 + (BACK ? 9 : 0);
    dst[row0] = vs[0]; dst[row1] = vs[1]; dst[8] = vs[8];
}

__global__ void __launch_bounds__(256, 1) rnn1_kernel(
    const float* __restrict__ x,
    const float* __restrict__ wih_f, const float* __restrict__ whh_f,
    const float* __restrict__ bih_f, const float* __restrict__ bhh_f,
    const float* __restrict__ wih_b, const float* __restrict__ whh_b,
    const float* __restrict__ bih_b, const float* __restrict__ bhh_b,
    int T, int B)
{
    int gtid = blockIdx.x * blockDim.x + threadIdx.x;
    int r     = gtid & 3;
    int chain = gtid >> 2;         // [0, 2B); first B fwd, second B bwd
    if (chain < B) {
        rnn1_body<false>(chain, r, x, wih_f, whh_f, bih_f, bhh_f, T);
    } else {
        rnn1_body<true>(chain - B, r, x, wih_b, whh_b, bih_b, bhh_b, T);
    }
}

// ---------------------------------------------------------------------------
// RNN2 + projection: warp per batch, smem h-broadcast, split accumulators.
// (R8 version, best measured ~21us)
// ---------------------------------------------------------------------------
#define ROWF 36  // padded row stride (floats): 16B-aligned, conflict-free

__global__ void __launch_bounds__(128) rnn2_kernel(
    const float* __restrict__ wih2, const float* __restrict__ whh2,
    const float* __restrict__ bih2, const float* __restrict__ bhh2,
    const float* __restrict__ wout, const float* __restrict__ bout,
    float* __restrict__ out, int B)
{
    __shared__ __align__(16) float hbuf[4][25 * ROWF];
    __shared__ float wsm[96];

    int tid = threadIdx.x;
    int wid = tid >> 5;
    int lane = tid & 31;
    int b = blockIdx.x * 4 + wid;

    if (tid < 96) wsm[tid] = __ldg(wout + tid);
    __syncthreads();
    if (b >= B) return;

    float WHR[32];
    {
        const float4* wr = reinterpret_cast<const float4*>(whh2 + lane * 32);
#pragma unroll
        for (int q = 0; q < 8; q++) {
            float4 v = __ldg(wr + q);
            WHR[4 * q + 0] = SC * v.x; WHR[4 * q + 1] = SC * v.y;
            WHR[4 * q + 2] = SC * v.z; WHR[4 * q + 3] = SC * v.w;
        }
    }
    float bi = SC * (__ldg(bih2 + lane) + __ldg(bhh2 + lane));

    // step 0: input y from g_y, two partial chains
    const float* yb = g_y + (size_t)b * 18;
    float ac0 = bi, ac1 = 0.0f;
#pragma unroll
    for (int j = 0; j < 9; j++)
        ac0 = fmaf(SC * __ldg(wih2 + lane * 18 + j), __ldg(yb + j), ac0);
#pragma unroll
    for (int j = 9; j < 18; j++)
        ac1 = fmaf(SC * __ldg(wih2 + lane * 18 + j), __ldg(yb + j), ac1);
    float h = tanh_sc(ac0 + ac1);

    float* hr = hbuf[wid];
    hr[lane] = h;
    __syncwarp();

#pragma unroll 1
    for (int t = 1; t < 25; t++) {
        const float4* rp = reinterpret_cast<const float4*>(hr + (t - 1) * ROWF);
        float p0 = bi, p1 = 0.0f, p2 = 0.0f, p3 = 0.0f;
#pragma unroll
        for (int q = 0; q < 8; q++) {
            float4 v = rp[q];
            float* pp = (q < 2) ? &p0 : ((q < 4) ? &p1 : ((q < 6) ? &p2 : &p3));
            *pp = fmaf(WHR[4 * q + 0], v.x, *pp);
            *pp = fmaf(WHR[4 * q + 1], v.y, *pp);
            *pp = fmaf(WHR[4 * q + 2], v.z, *pp);
            *pp = fmaf(WHR[4 * q + 3], v.w, *pp);
        }
        h = tanh_sc((p0 + p1) + (p2 + p3));
        hr[t * ROWF + lane] = h;
        __syncwarp();
    }

    // epilogue: 75 outputs -> lanes (idx = lane, lane+32, lane+64)
    float bo0 = __ldg(bout + 0), bo1 = __ldg(bout + 1), bo2 = __ldg(bout + 2);
    float* ob = out + (size_t)b * 75;
#pragma unroll
    for (int k = 0; k < 3; k++) {
        int idx = lane + 32 * k;
        if (idx < 75) {
            int t = idx / 3;
            int o = idx - 3 * t;
            const float4* rp = reinterpret_cast<const float4*>(hr + t * ROWF);
            float p0 = (o == 0) ? bo0 : ((o == 1) ? bo1 : bo2);
            float p1 = 0.0f, p2 = 0.0f, p3 = 0.0f;
#pragma unroll
            for (int q = 0; q < 8; q++) {
                float4 v = rp[q];
                float* pp = (q < 2) ? &p0 : ((q < 4) ? &p1 : ((q < 6) ? &p2 : &p3));
                *pp = fmaf(wsm[o * 32 + 4 * q + 0], v.x, *pp);
                *pp = fmaf(wsm[o * 32 + 4 * q + 1], v.y, *pp);
                *pp = fmaf(wsm[o * 32 + 4 * q + 2], v.z, *pp);
                *pp = fmaf(wsm[o * 32 + 4 * q + 3], v.w, *pp);
            }
            ob[idx] = (p0 + p1) + (p2 + p3);
        }
    }
}

// ---------------------------------------------------------------------------
extern "C" void kernel_launch(void* const* d_in, const int* in_sizes, int n_in,
                              void* d_out, int out_size)
{
    const float* x      = (const float*)d_in[0];
    const float* wih_f  = (const float*)d_in[1];
    const float* whh_f  = (const float*)d_in[2];
    const float* bih_f  = (const float*)d_in[3];
    const float* bhh_f  = (const float*)d_in[4];
    const float* wih_b  = (const float*)d_in[5];
    const float* whh_b  = (const float*)d_in[6];
    const float* bih_b  = (const float*)d_in[7];
    const float* bhh_b  = (const float*)d_in[8];
    const float* wih2   = (const float*)d_in[9];
    const float* whh2   = (const float*)d_in[10];
    const float* bih2   = (const float*)d_in[11];
    const float* bhh2   = (const float*)d_in[12];
    const float* wout   = (const float*)d_in[13];
    const float* bout   = (const float*)d_in[14];
    float* out = (float*)d_out;

    int B = out_size / 75;                 // 4096
    int T = in_sizes[0] / (B * 5);         // 2048

    // 4 lanes/chain, 1 chain/thread: 2B chains * 4 = 8*B threads.
    // Blocks of 256 -> 128 blocks -> 1 block/SM -> 2 warps per SMSP.
    int blocks1 = (8 * B) / 256;           // 128
    rnn1_kernel<<<blocks1, 256>>>(x, wih_f, whh_f, bih_f, bhh_f,
                                  wih_b, whh_b, bih_b, bhh_b, T, B);

    rnn2_kernel<<<B / 4, 128>>>(wih2, whh2, bih2, bhh2, wout, bout, out, B);
}